// round 2
// baseline (speedup 1.0000x reference)
#include <cuda_runtime.h>
#include <stdint.h>

#define NCOMP 256
#define PPB   8   // pairs per block

// Bit-packed tables indexed [ihi*256 + j], bit L refers to i = ihi*32 + L:
//   g_sgn: 1 iff sign(j, j^i) == -1
//   g_wed: 1 iff wedge term   (j subset of i)
//   g_inn: 1 iff inner term   ((j&i)==0 or i subset of j)
__device__ uint32_t g_sgn[8 * 256];
__device__ uint32_t g_wed[8 * 256];
__device__ uint32_t g_inn[8 * 256];

__global__ void build_tables_kernel() {
    int t    = blockIdx.x * blockDim.x + threadIdx.x;   // 0..65535
    int lane = t & 31;
    int j    = (t >> 5) & 255;
    int ihi  = t >> 13;
    int i    = (ihi << 5) | lane;
    int k    = j ^ i;
    int par  = 0;
#pragma unroll
    for (int d = 1; d < 8; ++d) par ^= __popc((j >> d) & k);
    unsigned ws = __ballot_sync(0xFFFFFFFFu, par & 1);
    unsigned ww = __ballot_sync(0xFFFFFFFFu, (j & ~i & 255) == 0);
    unsigned wi = __ballot_sync(0xFFFFFFFFu, ((j & i) == 0) || ((i & ~j & 255) == 0));
    if (lane == 0) {
        g_sgn[(ihi << 8) + j] = ws;
        g_wed[(ihi << 8) + j] = ww;
        g_inn[(ihi << 8) + j] = wi;
    }
}

__global__ __launch_bounds__(256, 1) void clifford_kernel(
    const float* __restrict__ A, const float* __restrict__ B,
    float* __restrict__ out, int npairs)
{
    // As[h*256 + j] packs pairs (p0+4h .. p0+4h+3) at component j as 2x f32x2.
    __shared__ ulonglong2 As[2 * NCOMP];
    __shared__ ulonglong2 Bs[2 * NCOMP];
    __shared__ uint32_t   Ssh[8 * 256];
    __shared__ uint32_t   Wsh[8 * 256];
    __shared__ uint32_t   Ish[8 * 256];

    const int tid = threadIdx.x;
    const int p0  = blockIdx.x * PPB;

    // ---- stage A, B pair-interleaved ----
#pragma unroll
    for (int h = 0; h < 2; ++h) {
        float4 v;
        v.x = A[(size_t)(p0 + 4 * h + 0) * NCOMP + tid];
        v.y = A[(size_t)(p0 + 4 * h + 1) * NCOMP + tid];
        v.z = A[(size_t)(p0 + 4 * h + 2) * NCOMP + tid];
        v.w = A[(size_t)(p0 + 4 * h + 3) * NCOMP + tid];
        *reinterpret_cast<float4*>(&As[h * NCOMP + tid]) = v;
        v.x = B[(size_t)(p0 + 4 * h + 0) * NCOMP + tid];
        v.y = B[(size_t)(p0 + 4 * h + 1) * NCOMP + tid];
        v.z = B[(size_t)(p0 + 4 * h + 2) * NCOMP + tid];
        v.w = B[(size_t)(p0 + 4 * h + 3) * NCOMP + tid];
        *reinterpret_cast<float4*>(&Bs[h * NCOMP + tid]) = v;
    }
    // ---- stage tables (2048 words each = 512 uint4) ----
#pragma unroll
    for (int r = 0; r < 2; ++r) {
        reinterpret_cast<uint4*>(Ssh)[tid + 256 * r] = reinterpret_cast<const uint4*>(g_sgn)[tid + 256 * r];
        reinterpret_cast<uint4*>(Wsh)[tid + 256 * r] = reinterpret_cast<const uint4*>(g_wed)[tid + 256 * r];
        reinterpret_cast<uint4*>(Ish)[tid + 256 * r] = reinterpret_cast<const uint4*>(g_inn)[tid + 256 * r];
    }
    __syncthreads();

    const int i     = tid;
    const int lane  = tid & 31;
    const int shamt = 31 - lane;
    const uint32_t* __restrict__ Srow = Ssh + ((tid >> 5) << 8);
    const uint32_t* __restrict__ Wrow = Wsh + ((tid >> 5) << 8);
    const uint32_t* __restrict__ Irow = Ish + ((tid >> 5) << 8);

    // 4 packed-accumulators (pairs 2-wide) per product
    unsigned long long G0 = 0, G1 = 0, G2 = 0, G3 = 0;
    unsigned long long W0 = 0, W1 = 0, W2 = 0, W3 = 0;
    unsigned long long I0 = 0, I1 = 0, I2 = 0, I3 = 0;

#pragma unroll 2
    for (int j4 = 0; j4 < NCOMP / 4; ++j4) {
        const int j = j4 << 2;
        const uint4 s4 = *reinterpret_cast<const uint4*>(Srow + j);
        const uint4 w4 = *reinterpret_cast<const uint4*>(Wrow + j);
        const uint4 i4 = *reinterpret_cast<const uint4*>(Irow + j);

#define DO_Q(QOFF, SW, WD, ID)                                                     \
        {                                                                          \
            const int jj = j + (QOFF);                                             \
            const uint32_t sm = ((SW) << shamt) & 0x80000000u;                     \
            unsigned long long sm2;                                                \
            asm("mov.b64 %0, {%1,%1};" : "=l"(sm2) : "r"(sm));                     \
            const int wsig = (int)((WD) << shamt);  /* bit31 = wedge flag */       \
            const int isig = (int)((ID) << shamt);  /* bit31 = inner flag */       \
            const int kx = jj ^ i;                                                 \
            const ulonglong2 av0 = As[jj];                                         \
            const ulonglong2 av1 = As[NCOMP + jj];                                 \
            const ulonglong2 bv0 = Bs[kx];                                         \
            const ulonglong2 bv1 = Bs[NCOMP + kx];                                 \
            const unsigned long long a0 = av0.x ^ sm2;                             \
            const unsigned long long a1 = av0.y ^ sm2;                             \
            const unsigned long long a2 = av1.x ^ sm2;                             \
            const unsigned long long a3 = av1.y ^ sm2;                             \
            asm("fma.rn.f32x2 %0, %4, %5, %0;\n\t"                                 \
                "fma.rn.f32x2 %1, %6, %7, %1;\n\t"                                 \
                "fma.rn.f32x2 %2, %8, %9, %2;\n\t"                                 \
                "fma.rn.f32x2 %3, %10, %11, %3;"                                   \
                : "+l"(G0), "+l"(G1), "+l"(G2), "+l"(G3)                           \
                : "l"(a0), "l"(bv0.x), "l"(a1), "l"(bv0.y),                        \
                  "l"(a2), "l"(bv1.x), "l"(a3), "l"(bv1.y));                       \
            asm("{\n\t"                                                            \
                ".reg .pred p;\n\t"                                                \
                "setp.lt.s32 p, %12, 0;\n\t"                                       \
                "@p fma.rn.f32x2 %0, %4, %5, %0;\n\t"                              \
                "@p fma.rn.f32x2 %1, %6, %7, %1;\n\t"                              \
                "@p fma.rn.f32x2 %2, %8, %9, %2;\n\t"                              \
                "@p fma.rn.f32x2 %3, %10, %11, %3;\n\t"                            \
                "}"                                                                \
                : "+l"(W0), "+l"(W1), "+l"(W2), "+l"(W3)                           \
                : "l"(a0), "l"(bv0.x), "l"(a1), "l"(bv0.y),                        \
                  "l"(a2), "l"(bv1.x), "l"(a3), "l"(bv1.y), "r"(wsig));            \
            asm("{\n\t"                                                            \
                ".reg .pred p;\n\t"                                                \
                "setp.lt.s32 p, %12, 0;\n\t"                                       \
                "@p fma.rn.f32x2 %0, %4, %5, %0;\n\t"                              \
                "@p fma.rn.f32x2 %1, %6, %7, %1;\n\t"                              \
                "@p fma.rn.f32x2 %2, %8, %9, %2;\n\t"                              \
                "@p fma.rn.f32x2 %3, %10, %11, %3;\n\t"                            \
                "}"                                                                \
                : "+l"(I0), "+l"(I1), "+l"(I2), "+l"(I3)                           \
                : "l"(a0), "l"(bv0.x), "l"(a1), "l"(bv0.y),                        \
                  "l"(a2), "l"(bv1.x), "l"(a3), "l"(bv1.y), "r"(isig));            \
        }

        DO_Q(0, s4.x, w4.x, i4.x);
        DO_Q(1, s4.y, w4.y, i4.y);
        DO_Q(2, s4.z, w4.z, i4.z);
        DO_Q(3, s4.w, w4.w, i4.w);
#undef DO_Q
    }

    // ---- store: out layout [3, npairs, NCOMP]; acc g holds pairs (2g, 2g+1) low/high ----
    const size_t plane = (size_t)npairs * NCOMP;
    float* __restrict__ og = out + (size_t)p0 * NCOMP + i;
    float* __restrict__ ow = og + plane;
    float* __restrict__ oi = og + 2 * plane;

#define LO(x) __uint_as_float((uint32_t)(x))
#define HI(x) __uint_as_float((uint32_t)((x) >> 32))
    og[0 * NCOMP] = LO(G0); og[1 * NCOMP] = HI(G0);
    og[2 * NCOMP] = LO(G1); og[3 * NCOMP] = HI(G1);
    og[4 * NCOMP] = LO(G2); og[5 * NCOMP] = HI(G2);
    og[6 * NCOMP] = LO(G3); og[7 * NCOMP] = HI(G3);
    ow[0 * NCOMP] = LO(W0); ow[1 * NCOMP] = HI(W0);
    ow[2 * NCOMP] = LO(W1); ow[3 * NCOMP] = HI(W1);
    ow[4 * NCOMP] = LO(W2); ow[5 * NCOMP] = HI(W2);
    ow[6 * NCOMP] = LO(W3); ow[7 * NCOMP] = HI(W3);
    oi[0 * NCOMP] = LO(I0); oi[1 * NCOMP] = HI(I0);
    oi[2 * NCOMP] = LO(I1); oi[3 * NCOMP] = HI(I1);
    oi[4 * NCOMP] = LO(I2); oi[5 * NCOMP] = HI(I2);
    oi[6 * NCOMP] = LO(I3); oi[7 * NCOMP] = HI(I3);
#undef LO
#undef HI
}

extern "C" void kernel_launch(void* const* d_in, const int* in_sizes, int n_in,
                              void* d_out, int out_size)
{
    const float* A = (const float*)d_in[0];
    const float* B = (const float*)d_in[1];
    float* out = (float*)d_out;

    const int npairs = in_sizes[0] / NCOMP;   // 1024

    build_tables_kernel<<<256, 256>>>();
    clifford_kernel<<<npairs / PPB, 256>>>(A, B, out, npairs);
}

// round 3
// speedup vs baseline: 1.4840x; 1.4840x over previous
#include <cuda_runtime.h>
#include <stdint.h>

#define NCOMP 256
#define PPB   8     // pairs per block
#define TPB   512   // two j-halves x 256 components

// Bit-packed sign table: g_sgn[ihi*256 + j], bit L = 1 iff sign(j, j ^ (ihi*32+L)) == -1
__device__ uint32_t g_sgn[8 * 256];

__global__ void build_sign_kernel() {
    int t    = blockIdx.x * blockDim.x + threadIdx.x;   // 0..65535
    int lane = t & 31;
    int j    = (t >> 5) & 255;
    int ihi  = t >> 13;
    int i    = (ihi << 5) | lane;
    int k    = j ^ i;
    int par  = 0;
#pragma unroll
    for (int d = 1; d < 8; ++d) par ^= __popc((j >> d) & k);
    unsigned w = __ballot_sync(0xFFFFFFFFu, par & 1);
    if (lane == 0) g_sgn[(ihi << 8) + j] = w;
}

__global__ __launch_bounds__(TPB, 1) void clifford_kernel(
    const float* __restrict__ A, const float* __restrict__ B,
    float* __restrict__ out, int npairs)
{
    // 24 KB pool:
    //   [0KB)  As0: float4[256]  pairs 0..3 of A at component j
    //   [4KB)  As1: float4[256]  pairs 4..7
    //   [8KB)  Bs0: float4[256]  pairs 0..3 of B
    //   [12KB) Bs1: float4[256]  pairs 4..7
    //   [16KB) Ssh: uint32[2048] sign table  (reused as Red: float4[256][2] after loop)
    __shared__ __align__(16) unsigned char pool[24576];
    float4*   As0 = reinterpret_cast<float4*>(pool);
    float4*   As1 = reinterpret_cast<float4*>(pool + 4096);
    float4*   Bs0 = reinterpret_cast<float4*>(pool + 8192);
    float4*   Bs1 = reinterpret_cast<float4*>(pool + 12288);
    uint32_t* Ssh = reinterpret_cast<uint32_t*>(pool + 16384);
    float4*   Red = reinterpret_cast<float4*>(pool + 16384);

    const int tid  = threadIdx.x;
    const int half = tid >> 8;       // 0: j in [0,128)   1: j in [128,256)
    const int i    = tid & 255;      // output component owned by this thread
    const int p0   = blockIdx.x * PPB;

    // ---- stage A/B pair-split: half h stages pairs 4h..4h+3 at component i ----
    {
        const float* Ap = A + (size_t)(p0 + 4 * half) * NCOMP + i;
        const float* Bp = B + (size_t)(p0 + 4 * half) * NCOMP + i;
        float4 va, vb;
        va.x = Ap[0 * NCOMP]; va.y = Ap[1 * NCOMP]; va.z = Ap[2 * NCOMP]; va.w = Ap[3 * NCOMP];
        vb.x = Bp[0 * NCOMP]; vb.y = Bp[1 * NCOMP]; vb.z = Bp[2 * NCOMP]; vb.w = Bp[3 * NCOMP];
        (half ? As1 : As0)[i] = va;
        (half ? Bs1 : Bs0)[i] = vb;
    }
    // ---- stage sign table: 2048 words = 512 uint4, one per thread ----
    reinterpret_cast<uint4*>(Ssh)[tid] = reinterpret_cast<const uint4*>(g_sgn)[tid];
    __syncthreads();

    const int lane  = i & 31;
    const int shamt = 31 - lane;
    const uint32_t* __restrict__ Srow = Ssh + ((i >> 5) << 8);
    const int jbase = half << 7;

    float g0=0.f,g1=0.f,g2=0.f,g3=0.f,g4=0.f,g5=0.f,g6=0.f,g7=0.f;   // geometric
    float w0=0.f,w1=0.f,w2=0.f,w3=0.f,w4=0.f,w5=0.f,w6=0.f,w7=0.f;   // wedge
    float n0=0.f,n1=0.f,n2=0.f,n3=0.f,n4=0.f,n5=0.f,n6=0.f,n7=0.f;   // inner

#pragma unroll 2
    for (int j4 = 0; j4 < 32; ++j4) {
        const int jb = jbase + (j4 << 2);
        const uint4 s4 = *reinterpret_cast<const uint4*>(Srow + jb);

#define DO_J(JOFF, SW)                                                          \
        {                                                                       \
            const int      jj  = jb + (JOFF);                                   \
            const uint32_t sm  = ((SW) << shamt) & 0x80000000u;                 \
            const int      kx  = jj ^ i;                                        \
            const bool     wed = ((jj & ~i & 255) == 0);                        \
            const bool     inn = (((jj & i) == 0) | ((i & ~jj) == 0));          \
            const float4 a0 = As0[jj];                                          \
            const float4 a1 = As1[jj];                                          \
            float4 b0 = Bs0[kx];                                                \
            float4 b1 = Bs1[kx];                                                \
            b0.x = __uint_as_float(__float_as_uint(b0.x) ^ sm);                 \
            b0.y = __uint_as_float(__float_as_uint(b0.y) ^ sm);                 \
            b0.z = __uint_as_float(__float_as_uint(b0.z) ^ sm);                 \
            b0.w = __uint_as_float(__float_as_uint(b0.w) ^ sm);                 \
            b1.x = __uint_as_float(__float_as_uint(b1.x) ^ sm);                 \
            b1.y = __uint_as_float(__float_as_uint(b1.y) ^ sm);                 \
            b1.z = __uint_as_float(__float_as_uint(b1.z) ^ sm);                 \
            b1.w = __uint_as_float(__float_as_uint(b1.w) ^ sm);                 \
            g0 = fmaf(a0.x, b0.x, g0); g1 = fmaf(a0.y, b0.y, g1);               \
            g2 = fmaf(a0.z, b0.z, g2); g3 = fmaf(a0.w, b0.w, g3);               \
            g4 = fmaf(a1.x, b1.x, g4); g5 = fmaf(a1.y, b1.y, g5);               \
            g6 = fmaf(a1.z, b1.z, g6); g7 = fmaf(a1.w, b1.w, g7);               \
            if (wed) {                                                          \
                w0 = fmaf(a0.x, b0.x, w0); w1 = fmaf(a0.y, b0.y, w1);           \
                w2 = fmaf(a0.z, b0.z, w2); w3 = fmaf(a0.w, b0.w, w3);           \
                w4 = fmaf(a1.x, b1.x, w4); w5 = fmaf(a1.y, b1.y, w5);           \
                w6 = fmaf(a1.z, b1.z, w6); w7 = fmaf(a1.w, b1.w, w7);           \
            }                                                                   \
            if (inn) {                                                          \
                n0 = fmaf(a0.x, b0.x, n0); n1 = fmaf(a0.y, b0.y, n1);           \
                n2 = fmaf(a0.z, b0.z, n2); n3 = fmaf(a0.w, b0.w, n3);           \
                n4 = fmaf(a1.x, b1.x, n4); n5 = fmaf(a1.y, b1.y, n5);           \
                n6 = fmaf(a1.z, b1.z, n6); n7 = fmaf(a1.w, b1.w, n7);           \
            }                                                                   \
        }

        DO_J(0, s4.x);
        DO_J(1, s4.y);
        DO_J(2, s4.z);
        DO_J(3, s4.w);
#undef DO_J
    }

    // ---- cross-half reduction (Red reuses the sign-table smem) + store ----
    __syncthreads();

    const size_t plane = (size_t)npairs * NCOMP;
    float* __restrict__ og = out + (size_t)p0 * NCOMP + i;

#define ROUND(V0,V1,V2,V3,V4,V5,V6,V7, DST)                                     \
    {                                                                           \
        if (half) {                                                             \
            Red[i * 2 + 0] = make_float4(V0, V1, V2, V3);                       \
            Red[i * 2 + 1] = make_float4(V4, V5, V6, V7);                       \
        }                                                                       \
        __syncthreads();                                                        \
        if (!half) {                                                            \
            const float4 r0 = Red[i * 2 + 0];                                   \
            const float4 r1 = Red[i * 2 + 1];                                   \
            (DST)[0 * NCOMP] = V0 + r0.x; (DST)[1 * NCOMP] = V1 + r0.y;         \
            (DST)[2 * NCOMP] = V2 + r0.z; (DST)[3 * NCOMP] = V3 + r0.w;         \
            (DST)[4 * NCOMP] = V4 + r1.x; (DST)[5 * NCOMP] = V5 + r1.y;         \
            (DST)[6 * NCOMP] = V6 + r1.z; (DST)[7 * NCOMP] = V7 + r1.w;         \
        }                                                                       \
        __syncthreads();                                                        \
    }

    ROUND(g0,g1,g2,g3,g4,g5,g6,g7, og)
    ROUND(w0,w1,w2,w3,w4,w5,w6,w7, og + plane)
    ROUND(n0,n1,n2,n3,n4,n5,n6,n7, og + 2 * plane)
#undef ROUND
}

extern "C" void kernel_launch(void* const* d_in, const int* in_sizes, int n_in,
                              void* d_out, int out_size)
{
    const float* A = (const float*)d_in[0];
    const float* B = (const float*)d_in[1];
    float* out = (float*)d_out;

    const int npairs = in_sizes[0] / NCOMP;   // 1024

    build_sign_kernel<<<256, 256>>>();
    clifford_kernel<<<npairs / PPB, TPB>>>(A, B, out, npairs);
}